// round 16
// baseline (speedup 1.0000x reference)
#include <cuda_runtime.h>
#include <cuda_bf16.h>
#include <math.h>
#include <stdint.h>

// ---------------- problem constants ----------------
#define N_NODES 10000
#define M_PAD   10112                 // 79 * 128
#define E_EDGES 80000
#define EE_TOT  (E_EDGES + N_NODES)   // 90000
#define D_INPUT 512
#define HDIM    1024
#define NHEADS  8
#define OUTD    256
#define LRELU_SLOPE 0.2f
#define LN_EPS 1e-5f
#define NSCAN_BLK ((N_NODES + 255) / 256)   // 40

// ---------------- device scratch (zero-initialized globals) ----------------
__device__ float g_h  [(size_t)N_NODES * HDIM];
__device__ float g_xlr[(size_t)N_NODES * 2 * HDIM];   // combined GEMM outputs
__device__ float g_biascat[2 * HDIM];
__device__ int g_deg[N_NODES];
__device__ int g_rowstart[N_NODES + 1];
__device__ int g_cursor[N_NODES];
__device__ int g_bsum[64];
__device__ int g_boff[64];
__device__ int g_esrc[EE_TOT];   // slot -> src node
__device__ int g_slot[EE_TOT];   // edge id -> slot
// split-bf16 operand buffers (16B-aligned for cp.async / uint4)
__device__ __align__(256) __nv_bfloat16 g_a3 [(size_t)M_PAD * 3 * HDIM];      // split of x
__device__ __align__(256) __nv_bfloat16 g_a3b[(size_t)M_PAD * 3 * HDIM];      // split of h
__device__ __align__(256) __nv_bfloat16 g_b3w[(size_t)2 * HDIM * 3 * HDIM];   // [<=2048, 3K]

__device__ __forceinline__ float eluf(float x) {
    return x > 0.f ? x : (expf(x) - 1.f);
}
__device__ __forceinline__ void split_bf16(float v, __nv_bfloat16& hi, __nv_bfloat16& lo) {
    hi = __float2bfloat16(v);
    lo = __float2bfloat16(v - __bfloat162float(hi));
}

// ================= PTX helpers (compute_100-safe: cp.async/ldmatrix/mma.sync) ====
__device__ __forceinline__ uint32_t smem_u32(const void* p) {
    uint32_t a;
    asm("{ .reg .u64 t; cvta.to.shared.u64 t, %1; cvt.u32.u64 %0, t; }" : "=r"(a) : "l"(p));
    return a;
}
__device__ __forceinline__ void cp16(uint32_t dst, const void* src) {
    asm volatile("cp.async.cg.shared.global [%0], [%1], 16;" :: "r"(dst), "l"(src) : "memory");
}
__device__ __forceinline__ void cp_commit() {
    asm volatile("cp.async.commit_group;" ::: "memory");
}
template<int N> __device__ __forceinline__ void cp_wait() {
    asm volatile("cp.async.wait_group %0;" :: "n"(N) : "memory");
}
__device__ __forceinline__ void ldm_x4(uint32_t& r0, uint32_t& r1, uint32_t& r2, uint32_t& r3,
                                       uint32_t addr) {
    asm volatile("ldmatrix.sync.aligned.m8n8.x4.shared.b16 {%0,%1,%2,%3}, [%4];"
                 : "=r"(r0), "=r"(r1), "=r"(r2), "=r"(r3) : "r"(addr));
}
__device__ __forceinline__ void mma16816(float* d,
                                         uint32_t a0, uint32_t a1, uint32_t a2, uint32_t a3,
                                         uint32_t b0, uint32_t b1) {
    asm volatile(
        "mma.sync.aligned.m16n8k16.row.col.f32.bf16.bf16.f32 "
        "{%0,%1,%2,%3}, {%4,%5,%6,%7}, {%8,%9}, {%0,%1,%2,%3};"
        : "+f"(d[0]), "+f"(d[1]), "+f"(d[2]), "+f"(d[3])
        : "r"(a0), "r"(a1), "r"(a2), "r"(a3), "r"(b0), "r"(b1));
}

// ---------------- CSR build ----------------
__global__ void k_init_counts() {
    int i = blockIdx.x * blockDim.x + threadIdx.x;
    if (i < N_NODES) { g_deg[i] = 0; g_cursor[i] = 0; }
}
__global__ void k_count(const int* __restrict__ ei) {
    int e = blockIdx.x * blockDim.x + threadIdx.x;
    if (e >= EE_TOT) return;
    int dst = (e < E_EDGES) ? ei[E_EDGES + e] : (e - E_EDGES);
    atomicAdd(&g_deg[dst], 1);
}
// device-wide scan: A) per-block inclusive, B) scan block sums, C) add offsets
__global__ void k_scan_a() {
    __shared__ int s[256];
    int b = blockIdx.x, t = threadIdx.x;
    int i = b * 256 + t;
    int v = (i < N_NODES) ? g_deg[i] : 0;
    s[t] = v;
    __syncthreads();
    #pragma unroll
    for (int off = 1; off < 256; off <<= 1) {
        int add = (t >= off) ? s[t - off] : 0;
        __syncthreads();
        s[t] += add;
        __syncthreads();
    }
    if (i < N_NODES) g_rowstart[i + 1] = s[t];
    if (t == 255) g_bsum[b] = s[255];
    if (b == 0 && t == 0) g_rowstart[0] = 0;
}
__global__ void k_scan_b() {
    __shared__ int s[64];
    int t = threadIdx.x;
    int v = (t < NSCAN_BLK) ? g_bsum[t] : 0;
    s[t] = v;
    __syncthreads();
    #pragma unroll
    for (int off = 1; off < 64; off <<= 1) {
        int add = (t >= off) ? s[t - off] : 0;
        __syncthreads();
        s[t] += add;
        __syncthreads();
    }
    g_boff[t] = s[t] - v;   // exclusive
}
__global__ void k_scan_c() {
    int b = blockIdx.x, t = threadIdx.x;
    int i = b * 256 + t;
    if (b > 0 && i < N_NODES) g_rowstart[i + 1] += g_boff[b];
}
__global__ void k_scatter(const int* __restrict__ ei) {
    int e = blockIdx.x * blockDim.x + threadIdx.x;
    if (e >= EE_TOT) return;
    int src, dst;
    if (e < E_EDGES) { src = ei[e]; dst = ei[E_EDGES + e]; }
    else             { src = dst = e - E_EDGES; }
    int pos  = atomicAdd(&g_cursor[dst], 1);
    int slot = g_rowstart[dst] + pos;
    g_esrc[slot] = src;
    g_slot[e]    = slot;
}

// ---------------- bias concat ----------------
__global__ void k_bcopy2(const float* __restrict__ a, int na,
                         const float* __restrict__ b, int nb) {
    int i = blockIdx.x * blockDim.x + threadIdx.x;
    if (i < na) g_biascat[i] = a[i];
    else if (i < na + nb) g_biascat[i] = b[i - na];
}
__global__ void k_bcopy3(const float* __restrict__ a, const float* __restrict__ b,
                         const float* __restrict__ c, int n) {
    int i = blockIdx.x * blockDim.x + threadIdx.x;
    if (i < n) g_biascat[i] = a[i];
    else if (i < 2 * n) g_biascat[i] = b[i - n];
    else if (i < 3 * n) g_biascat[i] = c[i - 2 * n];
}

// ---------------- initial activation split (input x only) ----------------
__global__ void k_asplit(const float* __restrict__ src, __nv_bfloat16* __restrict__ A3, int K) {
    int idx = blockIdx.x * blockDim.x + threadIdx.x;
    if (idx >= N_NODES * K) return;
    int m = idx / K, k = idx - m * K;
    __nv_bfloat16 hi, lo;
    split_bf16(src[idx], hi, lo);
    size_t base = (size_t)m * (3 * K);
    A3[base + k]         = hi;
    A3[base + K + k]     = lo;
    A3[base + 2 * K + k] = hi;
}

// ---- weight transpose+split, multi-source: virtual n spans the concatenated N.
__device__ __forceinline__ void wprep_body(const float* __restrict__ W,
                                           __nv_bfloat16* __restrict__ Wt3,
                                           int K, int N, int k0, int nloc0, int rowoff) {
    __shared__ float t[32][33];
    int tx = threadIdx.x, ty = threadIdx.y;   // (32, 8)
    #pragma unroll
    for (int i = 0; i < 4; i++)
        t[ty + 8 * i][tx] = W[(size_t)(k0 + ty + 8 * i) * N + nloc0 + tx];
    __syncthreads();
    #pragma unroll
    for (int i = 0; i < 4; i++) {
        int n = nloc0 + ty + 8 * i;
        int k = k0 + tx;
        __nv_bfloat16 hi, lo;
        split_bf16(t[tx][ty + 8 * i], hi, lo);
        size_t base = (size_t)(n + rowoff) * (3 * K);
        Wt3[base + k]         = hi;
        Wt3[base + K + k]     = hi;
        Wt3[base + 2 * K + k] = lo;
    }
}
__global__ void k_wprep1(const float* __restrict__ W, __nv_bfloat16* __restrict__ Wt3,
                         int K, int N) {
    wprep_body(W, Wt3, K, N, blockIdx.x * 32, blockIdx.y * 32, 0);
}
__global__ void k_wprep2(const float* __restrict__ Wa, const float* __restrict__ Wb,
                         __nv_bfloat16* __restrict__ Wt3, int K, int N) {
    int nv = blockIdx.y * 32;
    const float* W = (nv < N) ? Wa : Wb;
    int nloc = (nv < N) ? nv : nv - N;
    int rowoff = (nv < N) ? 0 : N;
    wprep_body(W, Wt3, K, N, blockIdx.x * 32, nloc, rowoff);
}
__global__ void k_wprep3(const float* __restrict__ Wa, const float* __restrict__ Wb,
                         const float* __restrict__ Wc,
                         __nv_bfloat16* __restrict__ Wt3, int K, int N) {
    int nv = blockIdx.y * 32;
    const float* W = (nv < N) ? Wa : (nv < 2 * N ? Wb : Wc);
    int nloc = (nv < N) ? nv : (nv < 2 * N ? nv - N : nv - 2 * N);
    int rowoff = (nv < N) ? 0 : (nv < 2 * N ? N : 2 * N);
    wprep_body(W, Wt3, K, N, blockIdx.x * 32, nloc, rowoff);
}

// ---------------- mma.sync GEMM (R10-proven): 128x128 tile, 2-stage, occ 2 -------
#define GSTAGE 32768
#define GSMEM_BYTES (2 * GSTAGE)

__device__ __forceinline__ void g_load_stage(uint32_t sbase,
                                             const __nv_bfloat16* A3, const __nv_bfloat16* B3,
                                             size_t arow, size_t brow, int K3, int k0, int tid) {
    uint32_t ab = sbase, bb = sbase + 16384;
    #pragma unroll
    for (int i = 0; i < 4; i++) {
        int chunk = tid + i * 256;
        int r  = chunk >> 3;
        int cb = chunk & 7;
        uint32_t off = (uint32_t)(r * 128 + cb * 16);
        off ^= (off >> 3) & 0x70;
        cp16(ab + off, A3 + (arow + r) * (size_t)K3 + k0 + cb * 8);
        cp16(bb + off, B3 + (brow + r) * (size_t)K3 + k0 + cb * 8);
    }
    cp_commit();
}

template<int ACT>
__global__ __launch_bounds__(256, 2)
void k_mma_gemm(const __nv_bfloat16* __restrict__ A3, const __nv_bfloat16* __restrict__ B3,
                const float* __restrict__ bias, float* __restrict__ C,
                __nv_bfloat16* __restrict__ a3out,
                int M, int K3, int Nc) {
    extern __shared__ char smem[];
    uint32_t sb = smem_u32(smem);

    const int tid  = threadIdx.x;
    const int wid  = tid >> 5, lane = tid & 31;
    const int wm   = wid >> 1;
    const int wn   = wid & 1;
    const int bn = blockIdx.x, bm = blockIdx.y;
    const size_t arow = (size_t)bm * 128;
    const size_t brow = (size_t)bn * 128;
    const int nch = K3 >> 6;

    float acc[2][8][4];
    #pragma unroll
    for (int i = 0; i < 2; i++)
        #pragma unroll
        for (int j = 0; j < 8; j++)
            #pragma unroll
            for (int q = 0; q < 4; q++) acc[i][j][q] = 0.f;

    const int a_r = wm * 32 + (lane & 15);
    const int a_c = (lane >> 4) << 3;
    const int b_r = wn * 64 + (lane & 7) + ((lane >> 4) << 3);
    const int b_c = ((lane >> 3) & 1) << 3;

    g_load_stage(sb, A3, B3, arow, brow, K3, 0, tid);

    for (int c = 0; c < nch; c++) {
        if (c + 1 < nch) {
            g_load_stage(sb + (uint32_t)((c + 1) & 1) * GSTAGE, A3, B3, arow, brow,
                         K3, (c + 1) << 6, tid);
            cp_wait<1>();
        } else {
            cp_wait<0>();
        }
        __syncthreads();

        uint32_t ab = sb + (uint32_t)(c & 1) * GSTAGE;
        uint32_t bb = ab + 16384;

        #pragma unroll
        for (int ks = 0; ks < 4; ks++) {
            uint32_t ra[2][4], rb[4][4];
            #pragma unroll
            for (int mt = 0; mt < 2; mt++) {
                uint32_t off = (uint32_t)((a_r + mt * 16) * 128 + (ks * 16 + a_c) * 2);
                off ^= (off >> 3) & 0x70;
                ldm_x4(ra[mt][0], ra[mt][1], ra[mt][2], ra[mt][3], ab + off);
            }
            #pragma unroll
            for (int nt2 = 0; nt2 < 4; nt2++) {
                uint32_t off = (uint32_t)((b_r + nt2 * 16) * 128 + (ks * 16 + b_c) * 2);
                off ^= (off >> 3) & 0x70;
                ldm_x4(rb[nt2][0], rb[nt2][1], rb[nt2][2], rb[nt2][3], bb + off);
            }
            #pragma unroll
            for (int mt = 0; mt < 2; mt++)
                #pragma unroll
                for (int nt = 0; nt < 8; nt++)
                    mma16816(acc[mt][nt],
                             ra[mt][0], ra[mt][1], ra[mt][2], ra[mt][3],
                             rb[nt >> 1][(nt & 1) * 2], rb[nt >> 1][(nt & 1) * 2 + 1]);
        }
        __syncthreads();
    }

    const int colbase = bn * 128 + wn * 64;
    #pragma unroll
    for (int mt = 0; mt < 2; mt++) {
        #pragma unroll
        for (int half = 0; half < 2; half++) {
            int r = bm * 128 + wm * 32 + mt * 16 + (lane >> 2) + half * 8;
            if (r >= M) continue;
            float* cp = C + (size_t)r * Nc + colbase;
            #pragma unroll
            for (int nt = 0; nt < 8; nt++) {
                int cc = nt * 8 + (lane & 3) * 2;
                float v0 = acc[mt][nt][half * 2 + 0] + bias[colbase + cc];
                float v1 = acc[mt][nt][half * 2 + 1] + bias[colbase + cc + 1];
                if (ACT == 1) { v0 = eluf(v0); v1 = eluf(v1); }
                cp[cc]     = v0;
                cp[cc + 1] = v1;
                if (ACT == 1 && a3out) {
                    int col = colbase + cc;
                    __nv_bfloat16 h0, l0, h1, l1;
                    split_bf16(v0, h0, l0);
                    split_bf16(v1, h1, l1);
                    size_t base = (size_t)r * (3 * Nc);
                    *(__nv_bfloat162*)&a3out[base + col]          = make_bfloat162(h0, h1);
                    *(__nv_bfloat162*)&a3out[base + Nc + col]     = make_bfloat162(l0, l1);
                    *(__nv_bfloat162*)&a3out[base + 2 * Nc + col] = make_bfloat162(h0, h1);
                }
            }
        }
    }
}

// ================ FUSED attention (layers 0/1, H=8): one block per dst ==========
// Software-pipelined edge loop (prefetch next src + feature vector).
template<int CHAN, int H, int THREADS>
__global__ __launch_bounds__(THREADS)
void k_attn_fused(const float* __restrict__ xl, const float* __restrict__ xr, int ld4,
                  const float* __restrict__ att,
                  const float* __restrict__ bc,
                  const float* __restrict__ resid, int rld4,
                  const float* __restrict__ gamma,
                  const float* __restrict__ beta, float* __restrict__ out,
                  __nv_bfloat16* __restrict__ a3out) {
    constexpr int V4 = CHAN / 4;
    static_assert(V4 == THREADS && CHAN / H == 128, "warp==head layout");

    int dst = blockIdx.x;
    int t = threadIdx.x;
    int w = t >> 5, lane = t & 31;

    int s0 = g_rowstart[dst], s1 = g_rowstart[dst + 1];

    const float4* xl4 = (const float4*)xl;
    float4 xr4  = ((const float4*)xr)[(size_t)dst * ld4 + t];
    float4 att4 = ((const float4*)att)[t];

    float m = -INFINITY, ssum = 0.f;
    float4 acc = make_float4(0.f, 0.f, 0.f, 0.f);

    float4 xv = make_float4(0.f, 0.f, 0.f, 0.f);
    if (s0 < s1) {
        int src0 = g_esrc[s0];
        xv = xl4[(size_t)src0 * ld4 + t];
    }
    for (int s = s0; s < s1; s++) {
        float4 xv_n = xv;
        if (s + 1 < s1) {
            int src_n = g_esrc[s + 1];
            xv_n = xl4[(size_t)src_n * ld4 + t];
        }
        float q0 = xv.x + xr4.x, q1 = xv.y + xr4.y, q2 = xv.z + xr4.z, q3 = xv.w + xr4.w;
        q0 = (q0 > 0.f) ? q0 : LRELU_SLOPE * q0;
        q1 = (q1 > 0.f) ? q1 : LRELU_SLOPE * q1;
        q2 = (q2 > 0.f) ? q2 : LRELU_SLOPE * q2;
        q3 = (q3 > 0.f) ? q3 : LRELU_SLOPE * q3;
        float part = q0 * att4.x + q1 * att4.y + q2 * att4.z + q3 * att4.w;
        #pragma unroll
        for (int off = 16; off > 0; off >>= 1)
            part += __shfl_xor_sync(0xFFFFFFFFu, part, off);
        float e = part;
        float mnew = fmaxf(m, e);
        float corr = expf(m - mnew);
        float p = expf(e - mnew);
        ssum = ssum * corr + p;
        acc.x = acc.x * corr + p * xv.x;
        acc.y = acc.y * corr + p * xv.y;
        acc.z = acc.z * corr + p * xv.z;
        acc.w = acc.w * corr + p * xv.w;
        m = mnew;
        xv = xv_n;
    }
    float inv = 1.f / ssum;
    acc.x *= inv; acc.y *= inv; acc.z *= inv; acc.w *= inv;

    float4 b = ((const float4*)bc)[t];
    float4 r = ((const float4*)resid)[(size_t)dst * rld4 + t];
    float v0 = eluf(acc.x + b.x) + r.x;
    float v1 = eluf(acc.y + b.y) + r.y;
    float v2 = eluf(acc.z + b.z) + r.z;
    float v3 = eluf(acc.w + b.w) + r.w;

    float ls  = v0 + v1 + v2 + v3;
    float lsq = v0*v0 + v1*v1 + v2*v2 + v3*v3;
    #pragma unroll
    for (int off = 16; off > 0; off >>= 1) {
        ls  += __shfl_xor_sync(0xFFFFFFFFu, ls,  off);
        lsq += __shfl_xor_sync(0xFFFFFFFFu, lsq, off);
    }
    constexpr int NW = THREADS / 32;
    __shared__ float ssm[NW], ssq[NW];
    if (lane == 0) { ssm[w] = ls; ssq[w] = lsq; }
    __syncthreads();
    if (t == 0) {
        float a = 0.f, q = 0.f;
        #pragma unroll
        for (int ww = 0; ww < NW; ww++) { a += ssm[ww]; q += ssq[ww]; }
        ssm[0] = a; ssq[0] = q;
    }
    __syncthreads();
    float mean = ssm[0] * (1.f / CHAN);
    float var  = ssq[0] * (1.f / CHAN) - mean * mean;
    float rstd = rsqrtf(var + LN_EPS);

    float4 gm = ((const float4*)gamma)[t];
    float4 bt = ((const float4*)beta)[t];
    float4 o;
    o.x = (v0 - mean) * rstd * gm.x + bt.x;
    o.y = (v1 - mean) * rstd * gm.y + bt.y;
    o.z = (v2 - mean) * rstd * gm.z + bt.z;
    o.w = (v3 - mean) * rstd * gm.w + bt.w;
    ((float4*)out)[(size_t)dst * V4 + t] = o;

    if (a3out) {
        __nv_bfloat16 h0, l0, h1, l1, h2, l2, h3, l3;
        split_bf16(o.x, h0, l0);
        split_bf16(o.y, h1, l1);
        split_bf16(o.z, h2, l2);
        split_bf16(o.w, h3, l3);
        size_t base = (size_t)dst * (3 * CHAN);
        int k = 4 * t;
        __nv_bfloat162 hp0 = make_bfloat162(h0, h1), hp1 = make_bfloat162(h2, h3);
        __nv_bfloat162 lp0 = make_bfloat162(l0, l1), lp1 = make_bfloat162(l2, l3);
        *(__nv_bfloat162*)&a3out[base + k]                = hp0;
        *(__nv_bfloat162*)&a3out[base + k + 2]            = hp1;
        *(__nv_bfloat162*)&a3out[base + CHAN + k]         = lp0;
        *(__nv_bfloat162*)&a3out[base + CHAN + k + 2]     = lp1;
        *(__nv_bfloat162*)&a3out[base + 2 * CHAN + k]     = hp0;
        *(__nv_bfloat162*)&a3out[base + 2 * CHAN + k + 2] = hp1;
    }
}

// ======== FUSED layer-2 attention (H=1, C=256): one WARP per dst =============
__global__ __launch_bounds__(256)
void k_attn_fused_l2(const float* __restrict__ xl, const float* __restrict__ xr, int ld4,
                     const float* __restrict__ att,
                     const float* __restrict__ bc,
                     const float* __restrict__ resid, int rld4,
                     const float* __restrict__ gamma,
                     const float* __restrict__ beta, float* __restrict__ out) {
    int w = threadIdx.x >> 5, lane = threadIdx.x & 31;
    int dst = blockIdx.x * 8 + w;
    if (dst >= N_NODES) return;

    int s0 = g_rowstart[dst], s1 = g_rowstart[dst + 1];

    const float4* xl4 = (const float4*)xl;
    const float4* xr4p = (const float4*)xr;
    float4 xrA = xr4p[(size_t)dst * ld4 + lane];
    float4 xrB = xr4p[(size_t)dst * ld4 + 32 + lane];
    float4 atA = ((const float4*)att)[lane];
    float4 atB = ((const float4*)att)[32 + lane];

    float m = -INFINITY, ssum = 0.f;
    float4 accA = make_float4(0.f, 0.f, 0.f, 0.f);
    float4 accB = make_float4(0.f, 0.f, 0.f, 0.f);

    float4 xa = make_float4(0.f, 0.f, 0.f, 0.f);
    float4 xb = make_float4(0.f, 0.f, 0.f, 0.f);
    if (s0 < s1) {
        int src0 = g_esrc[s0];
        xa = xl4[(size_t)src0 * ld4 + lane];
        xb = xl4[(size_t)src0 * ld4 + 32 + lane];
    }
    for (int s = s0; s < s1; s++) {
        float4 xa_n = xa, xb_n = xb;
        if (s + 1 < s1) {
            int src_n = g_esrc[s + 1];
            xa_n = xl4[(size_t)src_n * ld4 + lane];
            xb_n = xl4[(size_t)src_n * ld4 + 32 + lane];
        }
        float qa0 = xa.x + xrA.x, qa1 = xa.y + xrA.y, qa2 = xa.z + xrA.z, qa3 = xa.w + xrA.w;
        float qb0 = xb.x + xrB.x, qb1 = xb.y + xrB.y, qb2 = xb.z + xrB.z, qb3 = xb.w + xrB.w;
        qa0 = (qa0 > 0.f) ? qa0 : LRELU_SLOPE * qa0;
        qa1 = (qa1 > 0.f) ? qa1 : LRELU_SLOPE * qa1;
        qa2 = (qa2 > 0.f) ? qa2 : LRELU_SLOPE * qa2;
        qa3 = (qa3 > 0.f) ? qa3 : LRELU_SLOPE * qa3;
        qb0 = (qb0 > 0.f) ? qb0 : LRELU_SLOPE * qb0;
        qb1 = (qb1 > 0.f) ? qb1 : LRELU_SLOPE * qb1;
        qb2 = (qb2 > 0.f) ? qb2 : LRELU_SLOPE * qb2;
        qb3 = (qb3 > 0.f) ? qb3 : LRELU_SLOPE * qb3;
        float part = qa0 * atA.x + qa1 * atA.y + qa2 * atA.z + qa3 * atA.w
                   + qb0 * atB.x + qb1 * atB.y + qb2 * atB.z + qb3 * atB.w;
        #pragma unroll
        for (int off = 16; off > 0; off >>= 1)
            part += __shfl_xor_sync(0xFFFFFFFFu, part, off);
        float e = part;
        float mnew = fmaxf(m, e);
        float corr = expf(m - mnew);
        float p = expf(e - mnew);
        ssum = ssum * corr + p;
        accA.x = accA.x * corr + p * xa.x;
        accA.y = accA.y * corr + p * xa.y;
        accA.z = accA.z * corr + p * xa.z;
        accA.w = accA.w * corr + p * xa.w;
        accB.x = accB.x * corr + p * xb.x;
        accB.y = accB.y * corr + p * xb.y;
        accB.z = accB.z * corr + p * xb.z;
        accB.w = accB.w * corr + p * xb.w;
        m = mnew;
        xa = xa_n; xb = xb_n;
    }
    float inv = 1.f / ssum;
    accA.x *= inv; accA.y *= inv; accA.z *= inv; accA.w *= inv;
    accB.x *= inv; accB.y *= inv; accB.z *= inv; accB.w *= inv;

    float4 bA = ((const float4*)bc)[lane];
    float4 bB = ((const float4*)bc)[32 + lane];
    const float4* rr = (const float4*)resid;
    float4 rA = rr[(size_t)dst * rld4 + lane];
    float4 rB = rr[(size_t)dst * rld4 + 32 + lane];
    float vA0 = eluf(accA.x + bA.x) + rA.x;
    float vA1 = eluf(accA.y + bA.y) + rA.y;
    float vA2 = eluf(accA.z + bA.z) + rA.z;
    float vA3 = eluf(accA.w + bA.w) + rA.w;
    float vB0 = eluf(accB.x + bB.x) + rB.x;
    float vB1 = eluf(accB.y + bB.y) + rB.y;
    float vB2 = eluf(accB.z + bB.z) + rB.z;
    float vB3 = eluf(accB.w + bB.w) + rB.w;

    float ls  = vA0 + vA1 + vA2 + vA3 + vB0 + vB1 + vB2 + vB3;
    float lsq = vA0*vA0 + vA1*vA1 + vA2*vA2 + vA3*vA3
              + vB0*vB0 + vB1*vB1 + vB2*vB2 + vB3*vB3;
    #pragma unroll
    for (int off = 16; off > 0; off >>= 1) {
        ls  += __shfl_xor_sync(0xFFFFFFFFu, ls,  off);
        lsq += __shfl_xor_sync(0xFFFFFFFFu, lsq, off);
    }
    float mean = ls * (1.f / OUTD);
    float var  = lsq * (1.f / OUTD) - mean * mean;
    float rstd = rsqrtf(var + LN_EPS);

    float4 gA = ((const float4*)gamma)[lane];
    float4 gB = ((const float4*)gamma)[32 + lane];
    float4 tA = ((const float4*)beta)[lane];
    float4 tB = ((const float4*)beta)[32 + lane];
    float4 oA, oB;
    oA.x = (vA0 - mean) * rstd * gA.x + tA.x;
    oA.y = (vA1 - mean) * rstd * gA.y + tA.y;
    oA.z = (vA2 - mean) * rstd * gA.z + tA.z;
    oA.w = (vA3 - mean) * rstd * gA.w + tA.w;
    oB.x = (vB0 - mean) * rstd * gB.x + tB.x;
    oB.y = (vB1 - mean) * rstd * gB.y + tB.y;
    oB.z = (vB2 - mean) * rstd * gB.z + tB.z;
    oB.w = (vB3 - mean) * rstd * gB.w + tB.w;
    ((float4*)out)[(size_t)dst * (OUTD / 4) + lane]      = oA;
    ((float4*)out)[(size_t)dst * (OUTD / 4) + 32 + lane] = oB;
}

// ---------------- launch ----------------
extern "C" void kernel_launch(void* const* d_in, const int* in_sizes, int n_in,
                              void* d_out, int out_size) {
    (void)in_sizes; (void)n_in; (void)out_size;
    const float* x    = (const float*)d_in[0];
    const int*   ei   = (const int*)d_in[1];
    const float* W_in = (const float*)d_in[2];
    const float* b_in = (const float*)d_in[3];
    const float* Wl0  = (const float*)d_in[4];
    const float* bl0  = (const float*)d_in[5];
    const float* Wr0  = (const float*)d_in[6];
    const float* br0  = (const float*)d_in[7];
    const float* att0 = (const float*)d_in[8];
    const float* bc0  = (const float*)d_in[9];
    const float* g0   = (const float*)d_in[10];
    const float* be0  = (const float*)d_in[11];
    const float* Wl1  = (const float*)d_in[12];
    const float* bl1  = (const float*)d_in[13];
    const float* Wr1  = (const float*)d_in[14];
    const float* br1  = (const float*)d_in[15];
    const float* att1 = (const float*)d_in[16];
    const float* bc1  = (const float*)d_in[17];
    const float* g1   = (const float*)d_in[18];
    const float* be1  = (const float*)d_in[19];
    const float* Wl2  = (const float*)d_in[20];
    const float* bl2  = (const float*)d_in[21];
    const float* Wr2  = (const float*)d_in[22];
    const float* br2  = (const float*)d_in[23];
    const float* att2 = (const float*)d_in[24];
    const float* bc2  = (const float*)d_in[25];
    const float* g2   = (const float*)d_in[26];
    const float* be2  = (const float*)d_in[27];
    const float* Wres2 = (const float*)d_in[28];
    const float* bres2 = (const float*)d_in[29];
    float* out = (float*)d_out;

    float *h, *xlr;
    __nv_bfloat16 *a3, *a3b, *b3w;
    cudaGetSymbolAddress((void**)&h,    g_h);
    cudaGetSymbolAddress((void**)&xlr,  g_xlr);
    cudaGetSymbolAddress((void**)&a3,   g_a3);
    cudaGetSymbolAddress((void**)&a3b,  g_a3b);
    cudaGetSymbolAddress((void**)&b3w,  g_b3w);
    float* bcat;
    cudaGetSymbolAddress((void**)&bcat, g_biascat);

    cudaFuncSetAttribute(k_mma_gemm<0>, cudaFuncAttributeMaxDynamicSharedMemorySize, GSMEM_BYTES);
    cudaFuncSetAttribute(k_mma_gemm<1>, cudaFuncAttributeMaxDynamicSharedMemorySize, GSMEM_BYTES);

    // ---- CSR build (shared by all 3 layers) ----
    k_init_counts<<<(N_NODES + 255) / 256, 256>>>();
    k_count<<<(EE_TOT + 255) / 256, 256>>>(ei);
    k_scan_a<<<NSCAN_BLK, 256>>>();
    k_scan_b<<<1, 64>>>();
    k_scan_c<<<NSCAN_BLK, 256>>>();
    k_scatter<<<(EE_TOT + 255) / 256, 256>>>(ei);

    dim3 gemm_in(HDIM / 128, M_PAD / 128);       // (8, 79)
    dim3 gemm_hd2(2 * HDIM / 128, M_PAD / 128);  // (16, 79)
    dim3 gemm_l2(768 / 128, M_PAD / 128);        // (6, 79)
    dim3 wblk(32, 8);

    // ---- input projection: h = elu(x @ W_in + b_in), fused split -> a3b ----
    k_wprep1<<<dim3(D_INPUT / 32, HDIM / 32), wblk>>>(W_in, b3w, D_INPUT, HDIM);
    k_asplit<<<(N_NODES * D_INPUT + 255) / 256, 256>>>(x, a3, D_INPUT);
    k_mma_gemm<1><<<gemm_in, 256, GSMEM_BYTES>>>(a3, b3w, b_in, h, a3b,
                                                 N_NODES, 3 * D_INPUT, HDIM);

    // ---- layer 0: combined [Wl0 | Wr0] -> xlr, fused attention ----
    k_wprep2<<<dim3(HDIM / 32, 2 * HDIM / 32), wblk>>>(Wl0, Wr0, b3w, HDIM, HDIM);
    k_bcopy2<<<8, 256>>>(bl0, HDIM, br0, HDIM);
    k_mma_gemm<0><<<gemm_hd2, 256, GSMEM_BYTES>>>(a3b, b3w, bcat, xlr, nullptr,
                                                  N_NODES, 3 * HDIM, 2 * HDIM);
    k_attn_fused<HDIM, NHEADS, 256><<<N_NODES, 256>>>(xlr, xlr + HDIM, 2 * HDIM / 4,
                                                      att0, bc0, h, HDIM / 4,
                                                      g0, be0, h, a3b);

    // ---- layer 1 ----
    k_wprep2<<<dim3(HDIM / 32, 2 * HDIM / 32), wblk>>>(Wl1, Wr1, b3w, HDIM, HDIM);
    k_bcopy2<<<8, 256>>>(bl1, HDIM, br1, HDIM);
    k_mma_gemm<0><<<gemm_hd2, 256, GSMEM_BYTES>>>(a3b, b3w, bcat, xlr, nullptr,
                                                  N_NODES, 3 * HDIM, 2 * HDIM);
    k_attn_fused<HDIM, NHEADS, 256><<<N_NODES, 256>>>(xlr, xlr + HDIM, 2 * HDIM / 4,
                                                      att1, bc1, h, HDIM / 4,
                                                      g1, be1, h, a3b);

    // ---- layer 2: combined [Wl2 | Wr2 | Wres2] -> xlr[:, 0:768], fused attn ----
    k_wprep3<<<dim3(HDIM / 32, 3 * OUTD / 32), wblk>>>(Wl2, Wr2, Wres2, b3w, HDIM, OUTD);
    k_bcopy3<<<3, 256>>>(bl2, br2, bres2, OUTD);
    k_mma_gemm<0><<<gemm_l2, 256, GSMEM_BYTES>>>(a3b, b3w, bcat, xlr, nullptr,
                                                 N_NODES, 3 * HDIM, 768);
    k_attn_fused_l2<<<(N_NODES + 7) / 8, 256>>>(xlr, xlr + OUTD, 768 / 4,
                                                att2, bc2, xlr + 2 * OUTD, 768 / 4,
                                                g2, be2, out);
}

// round 17
// speedup vs baseline: 1.0292x; 1.0292x over previous
#include <cuda_runtime.h>
#include <cuda_bf16.h>
#include <math.h>
#include <stdint.h>

// ---------------- problem constants ----------------
#define N_NODES 10000
#define M_PAD   10112                 // 79 * 128
#define E_EDGES 80000
#define EE_TOT  (E_EDGES + N_NODES)   // 90000
#define D_INPUT 512
#define HDIM    1024
#define NHEADS  8
#define OUTD    256
#define LRELU_SLOPE 0.2f
#define LN_EPS 1e-5f
#define NSCAN_BLK ((N_NODES + 255) / 256)   // 40

// ---------------- device scratch (zero-initialized globals) ----------------
__device__ float g_h  [(size_t)N_NODES * HDIM];
__device__ float g_xlr[(size_t)N_NODES * 2 * HDIM];   // combined GEMM outputs
__device__ float g_biascat[2 * HDIM];
__device__ int g_deg[N_NODES];
__device__ int g_rowstart[N_NODES + 1];
__device__ int g_cursor[N_NODES];
__device__ int g_bsum[64];
__device__ int g_boff[64];
__device__ int g_esrc[EE_TOT];   // slot -> src node
__device__ int g_slot[EE_TOT];   // edge id -> slot
// split-bf16 operand buffers (16B-aligned for cp.async / uint4)
__device__ __align__(256) __nv_bfloat16 g_a3 [(size_t)M_PAD * 3 * HDIM];      // split of x
__device__ __align__(256) __nv_bfloat16 g_a3b[(size_t)M_PAD * 3 * HDIM];      // split of h
__device__ __align__(256) __nv_bfloat16 g_b3w[(size_t)2 * HDIM * 3 * HDIM];   // [<=2048, 3K]

__device__ __forceinline__ float eluf(float x) {
    return x > 0.f ? x : (expf(x) - 1.f);
}
__device__ __forceinline__ void split_bf16(float v, __nv_bfloat16& hi, __nv_bfloat16& lo) {
    hi = __float2bfloat16(v);
    lo = __float2bfloat16(v - __bfloat162float(hi));
}

// ================= PTX helpers (compute_100-safe: cp.async/ldmatrix/mma.sync) ====
__device__ __forceinline__ uint32_t smem_u32(const void* p) {
    uint32_t a;
    asm("{ .reg .u64 t; cvta.to.shared.u64 t, %1; cvt.u32.u64 %0, t; }" : "=r"(a) : "l"(p));
    return a;
}
__device__ __forceinline__ void cp16(uint32_t dst, const void* src) {
    asm volatile("cp.async.cg.shared.global [%0], [%1], 16;" :: "r"(dst), "l"(src) : "memory");
}
__device__ __forceinline__ void cp_commit() {
    asm volatile("cp.async.commit_group;" ::: "memory");
}
template<int N> __device__ __forceinline__ void cp_wait() {
    asm volatile("cp.async.wait_group %0;" :: "n"(N) : "memory");
}
__device__ __forceinline__ void ldm_x4(uint32_t& r0, uint32_t& r1, uint32_t& r2, uint32_t& r3,
                                       uint32_t addr) {
    asm volatile("ldmatrix.sync.aligned.m8n8.x4.shared.b16 {%0,%1,%2,%3}, [%4];"
                 : "=r"(r0), "=r"(r1), "=r"(r2), "=r"(r3) : "r"(addr));
}
__device__ __forceinline__ void mma16816(float* d,
                                         uint32_t a0, uint32_t a1, uint32_t a2, uint32_t a3,
                                         uint32_t b0, uint32_t b1) {
    asm volatile(
        "mma.sync.aligned.m16n8k16.row.col.f32.bf16.bf16.f32 "
        "{%0,%1,%2,%3}, {%4,%5,%6,%7}, {%8,%9}, {%0,%1,%2,%3};"
        : "+f"(d[0]), "+f"(d[1]), "+f"(d[2]), "+f"(d[3])
        : "r"(a0), "r"(a1), "r"(a2), "r"(a3), "r"(b0), "r"(b1));
}

// ---------------- CSR build ----------------
__global__ void k_init_counts() {
    int i = blockIdx.x * blockDim.x + threadIdx.x;
    if (i < N_NODES) { g_deg[i] = 0; g_cursor[i] = 0; }
}
__global__ void k_count(const int* __restrict__ ei) {
    int e = blockIdx.x * blockDim.x + threadIdx.x;
    if (e >= EE_TOT) return;
    int dst = (e < E_EDGES) ? ei[E_EDGES + e] : (e - E_EDGES);
    atomicAdd(&g_deg[dst], 1);
}
// device-wide scan: A) per-block inclusive, B) scan block sums, C) add offsets
__global__ void k_scan_a() {
    __shared__ int s[256];
    int b = blockIdx.x, t = threadIdx.x;
    int i = b * 256 + t;
    int v = (i < N_NODES) ? g_deg[i] : 0;
    s[t] = v;
    __syncthreads();
    #pragma unroll
    for (int off = 1; off < 256; off <<= 1) {
        int add = (t >= off) ? s[t - off] : 0;
        __syncthreads();
        s[t] += add;
        __syncthreads();
    }
    if (i < N_NODES) g_rowstart[i + 1] = s[t];
    if (t == 255) g_bsum[b] = s[255];
    if (b == 0 && t == 0) g_rowstart[0] = 0;
}
__global__ void k_scan_b() {
    __shared__ int s[64];
    int t = threadIdx.x;
    int v = (t < NSCAN_BLK) ? g_bsum[t] : 0;
    s[t] = v;
    __syncthreads();
    #pragma unroll
    for (int off = 1; off < 64; off <<= 1) {
        int add = (t >= off) ? s[t - off] : 0;
        __syncthreads();
        s[t] += add;
        __syncthreads();
    }
    g_boff[t] = s[t] - v;   // exclusive
}
__global__ void k_scan_c() {
    int b = blockIdx.x, t = threadIdx.x;
    int i = b * 256 + t;
    if (b > 0 && i < N_NODES) g_rowstart[i + 1] += g_boff[b];
}
__global__ void k_scatter(const int* __restrict__ ei) {
    int e = blockIdx.x * blockDim.x + threadIdx.x;
    if (e >= EE_TOT) return;
    int src, dst;
    if (e < E_EDGES) { src = ei[e]; dst = ei[E_EDGES + e]; }
    else             { src = dst = e - E_EDGES; }
    int pos  = atomicAdd(&g_cursor[dst], 1);
    int slot = g_rowstart[dst] + pos;
    g_esrc[slot] = src;
    g_slot[e]    = slot;
}

// ---------------- bias concat ----------------
__global__ void k_bcopy2(const float* __restrict__ a, int na,
                         const float* __restrict__ b, int nb) {
    int i = blockIdx.x * blockDim.x + threadIdx.x;
    if (i < na) g_biascat[i] = a[i];
    else if (i < na + nb) g_biascat[i] = b[i - na];
}
__global__ void k_bcopy3(const float* __restrict__ a, const float* __restrict__ b,
                         const float* __restrict__ c, int n) {
    int i = blockIdx.x * blockDim.x + threadIdx.x;
    if (i < n) g_biascat[i] = a[i];
    else if (i < 2 * n) g_biascat[i] = b[i - n];
    else if (i < 3 * n) g_biascat[i] = c[i - 2 * n];
}

// ---------------- initial activation split (input x only) ----------------
__global__ void k_asplit(const float* __restrict__ src, __nv_bfloat16* __restrict__ A3, int K) {
    int idx = blockIdx.x * blockDim.x + threadIdx.x;
    if (idx >= N_NODES * K) return;
    int m = idx / K, k = idx - m * K;
    __nv_bfloat16 hi, lo;
    split_bf16(src[idx], hi, lo);
    size_t base = (size_t)m * (3 * K);
    A3[base + k]         = hi;
    A3[base + K + k]     = lo;
    A3[base + 2 * K + k] = hi;
}

// ---- weight transpose+split, multi-source: virtual n spans the concatenated N.
__device__ __forceinline__ void wprep_body(const float* __restrict__ W,
                                           __nv_bfloat16* __restrict__ Wt3,
                                           int K, int N, int k0, int nloc0, int rowoff) {
    __shared__ float t[32][33];
    int tx = threadIdx.x, ty = threadIdx.y;   // (32, 8)
    #pragma unroll
    for (int i = 0; i < 4; i++)
        t[ty + 8 * i][tx] = W[(size_t)(k0 + ty + 8 * i) * N + nloc0 + tx];
    __syncthreads();
    #pragma unroll
    for (int i = 0; i < 4; i++) {
        int n = nloc0 + ty + 8 * i;
        int k = k0 + tx;
        __nv_bfloat16 hi, lo;
        split_bf16(t[tx][ty + 8 * i], hi, lo);
        size_t base = (size_t)(n + rowoff) * (3 * K);
        Wt3[base + k]         = hi;
        Wt3[base + K + k]     = hi;
        Wt3[base + 2 * K + k] = lo;
    }
}
__global__ void k_wprep1(const float* __restrict__ W, __nv_bfloat16* __restrict__ Wt3,
                         int K, int N) {
    wprep_body(W, Wt3, K, N, blockIdx.x * 32, blockIdx.y * 32, 0);
}
__global__ void k_wprep2(const float* __restrict__ Wa, const float* __restrict__ Wb,
                         __nv_bfloat16* __restrict__ Wt3, int K, int N) {
    int nv = blockIdx.y * 32;
    const float* W = (nv < N) ? Wa : Wb;
    int nloc = (nv < N) ? nv : nv - N;
    int rowoff = (nv < N) ? 0 : N;
    wprep_body(W, Wt3, K, N, blockIdx.x * 32, nloc, rowoff);
}
__global__ void k_wprep3(const float* __restrict__ Wa, const float* __restrict__ Wb,
                         const float* __restrict__ Wc,
                         __nv_bfloat16* __restrict__ Wt3, int K, int N) {
    int nv = blockIdx.y * 32;
    const float* W = (nv < N) ? Wa : (nv < 2 * N ? Wb : Wc);
    int nloc = (nv < N) ? nv : (nv < 2 * N ? nv - N : nv - 2 * N);
    int rowoff = (nv < N) ? 0 : (nv < 2 * N ? N : 2 * N);
    wprep_body(W, Wt3, K, N, blockIdx.x * 32, nloc, rowoff);
}

// ---------------- mma.sync GEMM (R10-proven): 128x128 tile, 2-stage, occ 2 -------
#define GSTAGE 32768
#define GSMEM_BYTES (2 * GSTAGE)

__device__ __forceinline__ void g_load_stage(uint32_t sbase,
                                             const __nv_bfloat16* A3, const __nv_bfloat16* B3,
                                             size_t arow, size_t brow, int K3, int k0, int tid) {
    uint32_t ab = sbase, bb = sbase + 16384;
    #pragma unroll
    for (int i = 0; i < 4; i++) {
        int chunk = tid + i * 256;
        int r  = chunk >> 3;
        int cb = chunk & 7;
        uint32_t off = (uint32_t)(r * 128 + cb * 16);
        off ^= (off >> 3) & 0x70;
        cp16(ab + off, A3 + (arow + r) * (size_t)K3 + k0 + cb * 8);
        cp16(bb + off, B3 + (brow + r) * (size_t)K3 + k0 + cb * 8);
    }
    cp_commit();
}

template<int ACT>
__global__ __launch_bounds__(256, 2)
void k_mma_gemm(const __nv_bfloat16* __restrict__ A3, const __nv_bfloat16* __restrict__ B3,
                const float* __restrict__ bias, float* __restrict__ C,
                __nv_bfloat16* __restrict__ a3out,
                int M, int K3, int Nc) {
    extern __shared__ char smem[];
    uint32_t sb = smem_u32(smem);

    const int tid  = threadIdx.x;
    const int wid  = tid >> 5, lane = tid & 31;
    const int wm   = wid >> 1;
    const int wn   = wid & 1;
    const int bn = blockIdx.x, bm = blockIdx.y;
    const size_t arow = (size_t)bm * 128;
    const size_t brow = (size_t)bn * 128;
    const int nch = K3 >> 6;

    float acc[2][8][4];
    #pragma unroll
    for (int i = 0; i < 2; i++)
        #pragma unroll
        for (int j = 0; j < 8; j++)
            #pragma unroll
            for (int q = 0; q < 4; q++) acc[i][j][q] = 0.f;

    const int a_r = wm * 32 + (lane & 15);
    const int a_c = (lane >> 4) << 3;
    const int b_r = wn * 64 + (lane & 7) + ((lane >> 4) << 3);
    const int b_c = ((lane >> 3) & 1) << 3;

    g_load_stage(sb, A3, B3, arow, brow, K3, 0, tid);

    for (int c = 0; c < nch; c++) {
        if (c + 1 < nch) {
            g_load_stage(sb + (uint32_t)((c + 1) & 1) * GSTAGE, A3, B3, arow, brow,
                         K3, (c + 1) << 6, tid);
            cp_wait<1>();
        } else {
            cp_wait<0>();
        }
        __syncthreads();

        uint32_t ab = sb + (uint32_t)(c & 1) * GSTAGE;
        uint32_t bb = ab + 16384;

        #pragma unroll
        for (int ks = 0; ks < 4; ks++) {
            uint32_t ra[2][4], rb[4][4];
            #pragma unroll
            for (int mt = 0; mt < 2; mt++) {
                uint32_t off = (uint32_t)((a_r + mt * 16) * 128 + (ks * 16 + a_c) * 2);
                off ^= (off >> 3) & 0x70;
                ldm_x4(ra[mt][0], ra[mt][1], ra[mt][2], ra[mt][3], ab + off);
            }
            #pragma unroll
            for (int nt2 = 0; nt2 < 4; nt2++) {
                uint32_t off = (uint32_t)((b_r + nt2 * 16) * 128 + (ks * 16 + b_c) * 2);
                off ^= (off >> 3) & 0x70;
                ldm_x4(rb[nt2][0], rb[nt2][1], rb[nt2][2], rb[nt2][3], bb + off);
            }
            #pragma unroll
            for (int mt = 0; mt < 2; mt++)
                #pragma unroll
                for (int nt = 0; nt < 8; nt++)
                    mma16816(acc[mt][nt],
                             ra[mt][0], ra[mt][1], ra[mt][2], ra[mt][3],
                             rb[nt >> 1][(nt & 1) * 2], rb[nt >> 1][(nt & 1) * 2 + 1]);
        }
        __syncthreads();
    }

    const int colbase = bn * 128 + wn * 64;
    #pragma unroll
    for (int mt = 0; mt < 2; mt++) {
        #pragma unroll
        for (int half = 0; half < 2; half++) {
            int r = bm * 128 + wm * 32 + mt * 16 + (lane >> 2) + half * 8;
            if (r >= M) continue;
            float* cp = C + (size_t)r * Nc + colbase;
            #pragma unroll
            for (int nt = 0; nt < 8; nt++) {
                int cc = nt * 8 + (lane & 3) * 2;
                float v0 = acc[mt][nt][half * 2 + 0] + bias[colbase + cc];
                float v1 = acc[mt][nt][half * 2 + 1] + bias[colbase + cc + 1];
                if (ACT == 1) { v0 = eluf(v0); v1 = eluf(v1); }
                cp[cc]     = v0;
                cp[cc + 1] = v1;
                if (ACT == 1 && a3out) {
                    int col = colbase + cc;
                    __nv_bfloat16 h0, l0, h1, l1;
                    split_bf16(v0, h0, l0);
                    split_bf16(v1, h1, l1);
                    size_t base = (size_t)r * (3 * Nc);
                    *(__nv_bfloat162*)&a3out[base + col]          = make_bfloat162(h0, h1);
                    *(__nv_bfloat162*)&a3out[base + Nc + col]     = make_bfloat162(l0, l1);
                    *(__nv_bfloat162*)&a3out[base + 2 * Nc + col] = make_bfloat162(h0, h1);
                }
            }
        }
    }
}

// ================ FUSED attention (layers 0/1, H=8): one block per dst ==========
// R15-proven version: simple dependent edge loop (no prefetch).
template<int CHAN, int H, int THREADS>
__global__ __launch_bounds__(THREADS)
void k_attn_fused(const float* __restrict__ xl, const float* __restrict__ xr, int ld4,
                  const float* __restrict__ att,
                  const float* __restrict__ bc,
                  const float* __restrict__ resid, int rld4,
                  const float* __restrict__ gamma,
                  const float* __restrict__ beta, float* __restrict__ out,
                  __nv_bfloat16* __restrict__ a3out) {
    constexpr int V4 = CHAN / 4;
    static_assert(V4 == THREADS && CHAN / H == 128, "warp==head layout");

    int dst = blockIdx.x;
    int t = threadIdx.x;
    int w = t >> 5, lane = t & 31;        // warp w = head w

    int s0 = g_rowstart[dst], s1 = g_rowstart[dst + 1];

    const float4* xl4 = (const float4*)xl;
    float4 xr4  = ((const float4*)xr)[(size_t)dst * ld4 + t];
    float4 att4 = ((const float4*)att)[t];

    float m = -INFINITY, ssum = 0.f;
    float4 acc = make_float4(0.f, 0.f, 0.f, 0.f);

    for (int s = s0; s < s1; s++) {
        int src = g_esrc[s];
        float4 xv = xl4[(size_t)src * ld4 + t];
        float q0 = xv.x + xr4.x, q1 = xv.y + xr4.y, q2 = xv.z + xr4.z, q3 = xv.w + xr4.w;
        q0 = (q0 > 0.f) ? q0 : LRELU_SLOPE * q0;
        q1 = (q1 > 0.f) ? q1 : LRELU_SLOPE * q1;
        q2 = (q2 > 0.f) ? q2 : LRELU_SLOPE * q2;
        q3 = (q3 > 0.f) ? q3 : LRELU_SLOPE * q3;
        float part = q0 * att4.x + q1 * att4.y + q2 * att4.z + q3 * att4.w;
        #pragma unroll
        for (int off = 16; off > 0; off >>= 1)
            part += __shfl_xor_sync(0xFFFFFFFFu, part, off);
        float e = part;
        float mnew = fmaxf(m, e);
        float corr = expf(m - mnew);
        float p = expf(e - mnew);
        ssum = ssum * corr + p;
        acc.x = acc.x * corr + p * xv.x;
        acc.y = acc.y * corr + p * xv.y;
        acc.z = acc.z * corr + p * xv.z;
        acc.w = acc.w * corr + p * xv.w;
        m = mnew;
    }
    float inv = 1.f / ssum;
    acc.x *= inv; acc.y *= inv; acc.z *= inv; acc.w *= inv;

    float4 b = ((const float4*)bc)[t];
    float4 r = ((const float4*)resid)[(size_t)dst * rld4 + t];
    float v0 = eluf(acc.x + b.x) + r.x;
    float v1 = eluf(acc.y + b.y) + r.y;
    float v2 = eluf(acc.z + b.z) + r.z;
    float v3 = eluf(acc.w + b.w) + r.w;

    float ls  = v0 + v1 + v2 + v3;
    float lsq = v0*v0 + v1*v1 + v2*v2 + v3*v3;
    #pragma unroll
    for (int off = 16; off > 0; off >>= 1) {
        ls  += __shfl_xor_sync(0xFFFFFFFFu, ls,  off);
        lsq += __shfl_xor_sync(0xFFFFFFFFu, lsq, off);
    }
    constexpr int NW = THREADS / 32;
    __shared__ float ssm[NW], ssq[NW];
    if (lane == 0) { ssm[w] = ls; ssq[w] = lsq; }
    __syncthreads();
    if (t == 0) {
        float a = 0.f, q = 0.f;
        #pragma unroll
        for (int ww = 0; ww < NW; ww++) { a += ssm[ww]; q += ssq[ww]; }
        ssm[0] = a; ssq[0] = q;
    }
    __syncthreads();
    float mean = ssm[0] * (1.f / CHAN);
    float var  = ssq[0] * (1.f / CHAN) - mean * mean;
    float rstd = rsqrtf(var + LN_EPS);

    float4 gm = ((const float4*)gamma)[t];
    float4 bt = ((const float4*)beta)[t];
    float4 o;
    o.x = (v0 - mean) * rstd * gm.x + bt.x;
    o.y = (v1 - mean) * rstd * gm.y + bt.y;
    o.z = (v2 - mean) * rstd * gm.z + bt.z;
    o.w = (v3 - mean) * rstd * gm.w + bt.w;
    ((float4*)out)[(size_t)dst * V4 + t] = o;

    if (a3out) {
        __nv_bfloat16 h0, l0, h1, l1, h2, l2, h3, l3;
        split_bf16(o.x, h0, l0);
        split_bf16(o.y, h1, l1);
        split_bf16(o.z, h2, l2);
        split_bf16(o.w, h3, l3);
        size_t base = (size_t)dst * (3 * CHAN);
        int k = 4 * t;
        __nv_bfloat162 hp0 = make_bfloat162(h0, h1), hp1 = make_bfloat162(h2, h3);
        __nv_bfloat162 lp0 = make_bfloat162(l0, l1), lp1 = make_bfloat162(l2, l3);
        *(__nv_bfloat162*)&a3out[base + k]                = hp0;
        *(__nv_bfloat162*)&a3out[base + k + 2]            = hp1;
        *(__nv_bfloat162*)&a3out[base + CHAN + k]         = lp0;
        *(__nv_bfloat162*)&a3out[base + CHAN + k + 2]     = lp1;
        *(__nv_bfloat162*)&a3out[base + 2 * CHAN + k]     = hp0;
        *(__nv_bfloat162*)&a3out[base + 2 * CHAN + k + 2] = hp1;
    }
}

// ======== FUSED layer-2 attention (H=1, C=256): one WARP per dst =============
// R15-proven version (no prefetch).
__global__ __launch_bounds__(256)
void k_attn_fused_l2(const float* __restrict__ xl, const float* __restrict__ xr, int ld4,
                     const float* __restrict__ att,
                     const float* __restrict__ bc,
                     const float* __restrict__ resid, int rld4,
                     const float* __restrict__ gamma,
                     const float* __restrict__ beta, float* __restrict__ out) {
    int w = threadIdx.x >> 5, lane = threadIdx.x & 31;
    int dst = blockIdx.x * 8 + w;
    if (dst >= N_NODES) return;

    int s0 = g_rowstart[dst], s1 = g_rowstart[dst + 1];

    const float4* xl4 = (const float4*)xl;
    const float4* xr4p = (const float4*)xr;
    float4 xrA = xr4p[(size_t)dst * ld4 + lane];
    float4 xrB = xr4p[(size_t)dst * ld4 + 32 + lane];
    float4 atA = ((const float4*)att)[lane];
    float4 atB = ((const float4*)att)[32 + lane];

    float m = -INFINITY, ssum = 0.f;
    float4 accA = make_float4(0.f, 0.f, 0.f, 0.f);
    float4 accB = make_float4(0.f, 0.f, 0.f, 0.f);

    for (int s = s0; s < s1; s++) {
        int src = g_esrc[s];
        float4 xa = xl4[(size_t)src * ld4 + lane];
        float4 xb = xl4[(size_t)src * ld4 + 32 + lane];
        float qa0 = xa.x + xrA.x, qa1 = xa.y + xrA.y, qa2 = xa.z + xrA.z, qa3 = xa.w + xrA.w;
        float qb0 = xb.x + xrB.x, qb1 = xb.y + xrB.y, qb2 = xb.z + xrB.z, qb3 = xb.w + xrB.w;
        qa0 = (qa0 > 0.f) ? qa0 : LRELU_SLOPE * qa0;
        qa1 = (qa1 > 0.f) ? qa1 : LRELU_SLOPE * qa1;
        qa2 = (qa2 > 0.f) ? qa2 : LRELU_SLOPE * qa2;
        qa3 = (qa3 > 0.f) ? qa3 : LRELU_SLOPE * qa3;
        qb0 = (qb0 > 0.f) ? qb0 : LRELU_SLOPE * qb0;
        qb1 = (qb1 > 0.f) ? qb1 : LRELU_SLOPE * qb1;
        qb2 = (qb2 > 0.f) ? qb2 : LRELU_SLOPE * qb2;
        qb3 = (qb3 > 0.f) ? qb3 : LRELU_SLOPE * qb3;
        float part = qa0 * atA.x + qa1 * atA.y + qa2 * atA.z + qa3 * atA.w
                   + qb0 * atB.x + qb1 * atB.y + qb2 * atB.z + qb3 * atB.w;
        #pragma unroll
        for (int off = 16; off > 0; off >>= 1)
            part += __shfl_xor_sync(0xFFFFFFFFu, part, off);
        float e = part;
        float mnew = fmaxf(m, e);
        float corr = expf(m - mnew);
        float p = expf(e - mnew);
        ssum = ssum * corr + p;
        accA.x = accA.x * corr + p * xa.x;
        accA.y = accA.y * corr + p * xa.y;
        accA.z = accA.z * corr + p * xa.z;
        accA.w = accA.w * corr + p * xa.w;
        accB.x = accB.x * corr + p * xb.x;
        accB.y = accB.y * corr + p * xb.y;
        accB.z = accB.z * corr + p * xb.z;
        accB.w = accB.w * corr + p * xb.w;
        m = mnew;
    }
    float inv = 1.f / ssum;
    accA.x *= inv; accA.y *= inv; accA.z *= inv; accA.w *= inv;
    accB.x *= inv; accB.y *= inv; accB.z *= inv; accB.w *= inv;

    float4 bA = ((const float4*)bc)[lane];
    float4 bB = ((const float4*)bc)[32 + lane];
    const float4* rr = (const float4*)resid;
    float4 rA = rr[(size_t)dst * rld4 + lane];
    float4 rB = rr[(size_t)dst * rld4 + 32 + lane];
    float vA0 = eluf(accA.x + bA.x) + rA.x;
    float vA1 = eluf(accA.y + bA.y) + rA.y;
    float vA2 = eluf(accA.z + bA.z) + rA.z;
    float vA3 = eluf(accA.w + bA.w) + rA.w;
    float vB0 = eluf(accB.x + bB.x) + rB.x;
    float vB1 = eluf(accB.y + bB.y) + rB.y;
    float vB2 = eluf(accB.z + bB.z) + rB.z;
    float vB3 = eluf(accB.w + bB.w) + rB.w;

    float ls  = vA0 + vA1 + vA2 + vA3 + vB0 + vB1 + vB2 + vB3;
    float lsq = vA0*vA0 + vA1*vA1 + vA2*vA2 + vA3*vA3
              + vB0*vB0 + vB1*vB1 + vB2*vB2 + vB3*vB3;
    #pragma unroll
    for (int off = 16; off > 0; off >>= 1) {
        ls  += __shfl_xor_sync(0xFFFFFFFFu, ls,  off);
        lsq += __shfl_xor_sync(0xFFFFFFFFu, lsq, off);
    }
    float mean = ls * (1.f / OUTD);
    float var  = lsq * (1.f / OUTD) - mean * mean;
    float rstd = rsqrtf(var + LN_EPS);

    float4 gA = ((const float4*)gamma)[lane];
    float4 gB = ((const float4*)gamma)[32 + lane];
    float4 tA = ((const float4*)beta)[lane];
    float4 tB = ((const float4*)beta)[32 + lane];
    float4 oA, oB;
    oA.x = (vA0 - mean) * rstd * gA.x + tA.x;
    oA.y = (vA1 - mean) * rstd * gA.y + tA.y;
    oA.z = (vA2 - mean) * rstd * gA.z + tA.z;
    oA.w = (vA3 - mean) * rstd * gA.w + tA.w;
    oB.x = (vB0 - mean) * rstd * gB.x + tB.x;
    oB.y = (vB1 - mean) * rstd * gB.y + tB.y;
    oB.z = (vB2 - mean) * rstd * gB.z + tB.z;
    oB.w = (vB3 - mean) * rstd * gB.w + tB.w;
    ((float4*)out)[(size_t)dst * (OUTD / 4) + lane]      = oA;
    ((float4*)out)[(size_t)dst * (OUTD / 4) + 32 + lane] = oB;
}

// ---------------- launch ----------------
extern "C" void kernel_launch(void* const* d_in, const int* in_sizes, int n_in,
                              void* d_out, int out_size) {
    (void)in_sizes; (void)n_in; (void)out_size;
    const float* x    = (const float*)d_in[0];
    const int*   ei   = (const int*)d_in[1];
    const float* W_in = (const float*)d_in[2];
    const float* b_in = (const float*)d_in[3];
    const float* Wl0  = (const float*)d_in[4];
    const float* bl0  = (const float*)d_in[5];
    const float* Wr0  = (const float*)d_in[6];
    const float* br0  = (const float*)d_in[7];
    const float* att0 = (const float*)d_in[8];
    const float* bc0  = (const float*)d_in[9];
    const float* g0   = (const float*)d_in[10];
    const float* be0  = (const float*)d_in[11];
    const float* Wl1  = (const float*)d_in[12];
    const float* bl1  = (const float*)d_in[13];
    const float* Wr1  = (const float*)d_in[14];
    const float* br1  = (const float*)d_in[15];
    const float* att1 = (const float*)d_in[16];
    const float* bc1  = (const float*)d_in[17];
    const float* g1   = (const float*)d_in[18];
    const float* be1  = (const float*)d_in[19];
    const float* Wl2  = (const float*)d_in[20];
    const float* bl2  = (const float*)d_in[21];
    const float* Wr2  = (const float*)d_in[22];
    const float* br2  = (const float*)d_in[23];
    const float* att2 = (const float*)d_in[24];
    const float* bc2  = (const float*)d_in[25];
    const float* g2   = (const float*)d_in[26];
    const float* be2  = (const float*)d_in[27];
    const float* Wres2 = (const float*)d_in[28];
    const float* bres2 = (const float*)d_in[29];
    float* out = (float*)d_out;

    float *h, *xlr;
    __nv_bfloat16 *a3, *a3b, *b3w;
    cudaGetSymbolAddress((void**)&h,    g_h);
    cudaGetSymbolAddress((void**)&xlr,  g_xlr);
    cudaGetSymbolAddress((void**)&a3,   g_a3);
    cudaGetSymbolAddress((void**)&a3b,  g_a3b);
    cudaGetSymbolAddress((void**)&b3w,  g_b3w);
    float* bcat;
    cudaGetSymbolAddress((void**)&bcat, g_biascat);

    cudaFuncSetAttribute(k_mma_gemm<0>, cudaFuncAttributeMaxDynamicSharedMemorySize, GSMEM_BYTES);
    cudaFuncSetAttribute(k_mma_gemm<1>, cudaFuncAttributeMaxDynamicSharedMemorySize, GSMEM_BYTES);

    // ---- CSR build (shared by all 3 layers) ----
    k_init_counts<<<(N_NODES + 255) / 256, 256>>>();
    k_count<<<(EE_TOT + 255) / 256, 256>>>(ei);
    k_scan_a<<<NSCAN_BLK, 256>>>();
    k_scan_b<<<1, 64>>>();
    k_scan_c<<<NSCAN_BLK, 256>>>();
    k_scatter<<<(EE_TOT + 255) / 256, 256>>>(ei);

    dim3 gemm_in(HDIM / 128, M_PAD / 128);       // (8, 79)
    dim3 gemm_hd2(2 * HDIM / 128, M_PAD / 128);  // (16, 79)
    dim3 gemm_l2(768 / 128, M_PAD / 128);        // (6, 79)
    dim3 wblk(32, 8);

    // ---- input projection: h = elu(x @ W_in + b_in), fused split -> a3b ----
    k_wprep1<<<dim3(D_INPUT / 32, HDIM / 32), wblk>>>(W_in, b3w, D_INPUT, HDIM);
    k_asplit<<<(N_NODES * D_INPUT + 255) / 256, 256>>>(x, a3, D_INPUT);
    k_mma_gemm<1><<<gemm_in, 256, GSMEM_BYTES>>>(a3, b3w, b_in, h, a3b,
                                                 N_NODES, 3 * D_INPUT, HDIM);

    // ---- layer 0: combined [Wl0 | Wr0] -> xlr, fused attention ----
    k_wprep2<<<dim3(HDIM / 32, 2 * HDIM / 32), wblk>>>(Wl0, Wr0, b3w, HDIM, HDIM);
    k_bcopy2<<<8, 256>>>(bl0, HDIM, br0, HDIM);
    k_mma_gemm<0><<<gemm_hd2, 256, GSMEM_BYTES>>>(a3b, b3w, bcat, xlr, nullptr,
                                                  N_NODES, 3 * HDIM, 2 * HDIM);
    k_attn_fused<HDIM, NHEADS, 256><<<N_NODES, 256>>>(xlr, xlr + HDIM, 2 * HDIM / 4,
                                                      att0, bc0, h, HDIM / 4,
                                                      g0, be0, h, a3b);

    // ---- layer 1 ----
    k_wprep2<<<dim3(HDIM / 32, 2 * HDIM / 32), wblk>>>(Wl1, Wr1, b3w, HDIM, HDIM);
    k_bcopy2<<<8, 256>>>(bl1, HDIM, br1, HDIM);
    k_mma_gemm<0><<<gemm_hd2, 256, GSMEM_BYTES>>>(a3b, b3w, bcat, xlr, nullptr,
                                                  N_NODES, 3 * HDIM, 2 * HDIM);
    k_attn_fused<HDIM, NHEADS, 256><<<N_NODES, 256>>>(xlr, xlr + HDIM, 2 * HDIM / 4,
                                                      att1, bc1, h, HDIM / 4,
                                                      g1, be1, h, a3b);

    // ---- layer 2: combined [Wl2 | Wr2 | Wres2] -> xlr[:, 0:768], fused attn ----
    k_wprep3<<<dim3(HDIM / 32, 3 * OUTD / 32), wblk>>>(Wl2, Wr2, Wres2, b3w, HDIM, OUTD);
    k_bcopy3<<<3, 256>>>(bl2, br2, bres2, OUTD);
    k_mma_gemm<0><<<gemm_l2, 256, GSMEM_BYTES>>>(a3b, b3w, bcat, xlr, nullptr,
                                                 N_NODES, 3 * HDIM, 768);
    k_attn_fused_l2<<<(N_NODES + 7) / 8, 256>>>(xlr, xlr + OUTD, 768 / 4,
                                                att2, bc2, xlr + 2 * OUTD, 768 / 4,
                                                g2, be2, out);
}